// round 12
// baseline (speedup 1.0000x reference)
#include <cuda_runtime.h>
#include <cstdint>

#define V 12288
#define CIN 16
#define COUT 32
#define KORD 5
#define NKS 3               // k-slices per pass  -> 96*3 = 288 CTAs = 1 wave @2/SM
#define KSL (V / NKS)       // 4096
#define CHK 64              // u per chunk
#define NCHK (KSL / CHK)    // 64
#define CV (CIN * V)
#define RSB 144             // B smem row stride bytes (conflict-free frags)
#define AST 272             // A (fp32) smem row stride bytes (16B-mult, 2-wf LDS.64)
#define NCTA (96 * NKS)     // 288

// fp32 scratch: T1..T3, per-kslice partials, grid-barrier counter
__device__ float g_T[3][CV];
__device__ float g_part[NKS][CV];
__device__ unsigned g_bar;   // monotonic (288 incr per barrier) -> graph-replay safe

// smem layout: 3 x A fp32 stage (128*272) | 2 x B split stage (BH 2304 + BL 2304)
#define A_STG  (128 * AST)            // 34816
#define B_OFF  (3 * A_STG)            // 104448
#define B_STG  (2 * 16 * RSB)         // 4608 (BH+BL)
#define BL_REL (16 * RSB)             // 2304
#define SMEM_DYN (B_OFF + 2 * B_STG)  // 113664

__device__ __forceinline__ uint32_t lds32(uint32_t a) {
    uint32_t v;
    asm volatile("ld.shared.b32 %0, [%1];" : "=r"(v) : "r"(a));
    return v;
}
__device__ __forceinline__ uint2 lds64(uint32_t a) {
    uint2 v;
    asm volatile("ld.shared.v2.u32 {%0,%1}, [%2];" : "=r"(v.x), "=r"(v.y) : "r"(a));
    return v;
}
__device__ __forceinline__ void sts64(uint32_t a, uint32_t w0, uint32_t w1) {
    asm volatile("st.shared.v2.b32 [%0], {%1,%2};" :: "r"(a), "r"(w0), "r"(w1) : "memory");
}
__device__ __forceinline__ void cp_async16(uint32_t dst, const void* src) {
    asm volatile("cp.async.cg.shared.global [%0], [%1], 16;\n" :: "r"(dst), "l"(src));
}
__device__ __forceinline__ void cp_commit() {
    asm volatile("cp.async.commit_group;\n");
}
template <int N>
__device__ __forceinline__ void cp_wait() {
    asm volatile("cp.async.wait_group %0;\n" :: "n"(N));
}

// split one fp32 pair -> bf16-hi pair (truncate) + bf16-lo pair (residual, RN)
__device__ __forceinline__ void split2(uint2 p, uint32_t& h, uint32_t& l) {
    h = __byte_perm(p.x, p.y, 0x7632);
    float l0 = __uint_as_float(p.x) - __uint_as_float(p.x & 0xFFFF0000u);
    float l1 = __uint_as_float(p.y) - __uint_as_float(p.y & 0xFFFF0000u);
    asm("cvt.rn.bf16x2.f32 %0, %1, %2;" : "=r"(l) : "f"(l1), "f"(l0));
}

// split fp32 x4 -> hi/lo tiles (B staging only)
__device__ __forceinline__ void split_sts(float4 f, uint32_t ah, uint32_t al) {
    uint32_t b0 = __float_as_uint(f.x), b1 = __float_as_uint(f.y);
    uint32_t b2 = __float_as_uint(f.z), b3 = __float_as_uint(f.w);
    uint32_t h0 = __byte_perm(b0, b1, 0x7632);
    uint32_t h1 = __byte_perm(b2, b3, 0x7632);
    float l0 = f.x - __uint_as_float(b0 & 0xFFFF0000u);
    float l1 = f.y - __uint_as_float(b1 & 0xFFFF0000u);
    float l2 = f.z - __uint_as_float(b2 & 0xFFFF0000u);
    float l3 = f.w - __uint_as_float(b3 & 0xFFFF0000u);
    uint32_t w0, w1;
    asm("cvt.rn.bf16x2.f32 %0, %1, %2;" : "=r"(w0) : "f"(l1), "f"(l0));
    asm("cvt.rn.bf16x2.f32 %0, %1, %2;" : "=r"(w1) : "f"(l3), "f"(l2));
    sts64(ah, h0, h1);
    sts64(al, w0, w1);
}

__device__ __forceinline__ void mma_bf16(float* c, uint32_t a0, uint32_t a1,
                                         uint32_t a2, uint32_t a3,
                                         uint32_t b0, uint32_t b1) {
    asm volatile("mma.sync.aligned.m16n8k16.row.col.f32.bf16.bf16.f32 "
                 "{%0,%1,%2,%3}, {%4,%5,%6,%7}, {%8,%9}, {%0,%1,%2,%3};"
                 : "+f"(c[0]), "+f"(c[1]), "+f"(c[2]), "+f"(c[3])
                 : "r"(a0), "r"(a1), "r"(a2), "r"(a3), "r"(b0), "r"(b1));
}

// software grid barrier: 288 CTAs co-resident (one wave); monotonic counter
__device__ __forceinline__ void grid_barrier(int tid) {
    __syncthreads();
    if (tid == 0) {
        __threadfence();
        unsigned old = atomicAdd(&g_bar, 1u) + 1u;
        unsigned target = ((old + (NCTA - 1u)) / NCTA) * NCTA;
        for (;;) {
            unsigned cur;
            asm volatile("ld.global.acquire.gpu.u32 %0, [%1];"
                         : "=r"(cur) : "l"(&g_bar));
            if (cur >= target) break;
            __nanosleep(64);
        }
    }
    __syncthreads();
}

// ---------------- pass body (cp.async A pipeline, 3-stage) ----------------
__device__ __forceinline__ void pass_body(
    const float* __restrict__ L, const float* __restrict__ B,
    uint32_t sb, int t, int warp, int lane, int vt, int ks)
{
    const int g    = lane >> 2;
    const int tc   = lane & 3;
    const int ub   = ks * KSL;

    // staging maps
    const int rh = t >> 4;           // 0..15
    const int cq = t & 15;           // 16B quad
    const float* Ag = L + (size_t)(vt * 128 + rh) * V + ub + cq * 4;
    const float* Bg = B + (size_t)rh * V + ub + cq * 4;
    const uint32_t a_dst = sb + (uint32_t)(rh * AST + cq * 16);   // + j*16*AST + buf
    const uint32_t b_dst = sb + B_OFF + (uint32_t)(rh * RSB + cq * 8);

    // fragment offsets
    const int vw = warp * 16;
    const uint32_t a_frag = sb + (uint32_t)((vw + g) * AST + tc * 8);
    const uint32_t b_frag = sb + B_OFF + (uint32_t)(g * RSB + tc * 4);

    float c0[4] = {0.f, 0.f, 0.f, 0.f};
    float c1[4] = {0.f, 0.f, 0.f, 0.f};

    // ---- prologue ----
    {
        float4 t0 = __ldg((const float4*)(Bg));          // B[0]
        split_sts(t0, b_dst, b_dst + BL_REL);            // -> Bbuf0
    }
    float4 lb = __ldg((const float4*)(Bg + CHK));        // B[1]
#pragma unroll
    for (int j = 0; j < 8; j++)                          // A[0] -> Abuf0
        cp_async16(a_dst + j * (16 * AST), Ag + (size_t)j * 16 * V);
    cp_commit();
#pragma unroll
    for (int j = 0; j < 8; j++)                          // A[1] -> Abuf1
        cp_async16(a_dst + A_STG + j * (16 * AST), Ag + (size_t)j * 16 * V + CHK);
    cp_commit();

#pragma unroll 1
    for (int c = 0; c < NCHK; c++) {
        float4 lbn;
        if (c + 2 < NCHK) lbn = __ldg((const float4*)(Bg + (c + 2) * CHK));

        cp_wait<0>();          // A[c] (and A[c+1]) landed for this thread
        __syncthreads();       // visibility + all warps done with compute c-1

        // stage B[c+1] -> Bbuf (c+1)%2 (reader compute c-1 finished)
        if (c + 1 < NCHK) {
            const uint32_t bo = b_dst + (uint32_t)(((c + 1) & 1) * B_STG);
            split_sts(lb, bo, bo + BL_REL);
        }
        // issue A[c+2] -> Abuf (c+2)%3 (reader compute c-1 finished)
        if (c + 2 < NCHK) {
            const uint32_t ao = a_dst + (uint32_t)(((c + 2) % 3) * A_STG);
            const float* as = Ag + (c + 2) * CHK;
#pragma unroll
            for (int j = 0; j < 8; j++)
                cp_async16(ao + j * (16 * AST), as + (size_t)j * 16 * V);
            cp_commit();
        }

        // compute chunk c: A fp32 frags split in-register
        const uint32_t abuf = a_frag + (uint32_t)((c % 3) * A_STG);
        const uint32_t bbuf = b_frag + (uint32_t)((c & 1) * B_STG);
#pragma unroll
        for (int s = 0; s < 4; s++) {
            const uint32_t ao = abuf + s * 64;
            const uint32_t bo = bbuf + s * 32;

            uint2 p00 = lds64(ao);                    // row g,   k pair 2tc
            uint2 p10 = lds64(ao + 8 * AST);          // row g+8, k pair 2tc
            uint2 p01 = lds64(ao + 32);               // row g,   k pair 2tc+8
            uint2 p11 = lds64(ao + 8 * AST + 32);     // row g+8, k pair 2tc+8
            uint32_t ah0, al0, ah1, al1, ah2, al2, ah3, al3;
            split2(p00, ah0, al0);
            split2(p10, ah1, al1);
            split2(p01, ah2, al2);
            split2(p11, ah3, al3);

            uint32_t bh0 = lds32(bo);
            uint32_t bh1 = lds32(bo + 16);
            uint32_t bl0 = lds32(bo + BL_REL);
            uint32_t bl1 = lds32(bo + BL_REL + 16);
            mma_bf16(c0, ah0, ah1, ah2, ah3, bh0, bh1);
            mma_bf16(c0, ah0, ah1, ah2, ah3, bl0, bl1);
            mma_bf16(c0, al0, al1, al2, al3, bh0, bh1);

            uint32_t ch0 = lds32(bo + 8 * RSB);
            uint32_t ch1 = lds32(bo + 8 * RSB + 16);
            uint32_t cl0 = lds32(bo + BL_REL + 8 * RSB);
            uint32_t cl1 = lds32(bo + BL_REL + 8 * RSB + 16);
            mma_bf16(c1, ah0, ah1, ah2, ah3, ch0, ch1);
            mma_bf16(c1, ah0, ah1, ah2, ah3, cl0, cl1);
            mma_bf16(c1, al0, al1, al2, al3, ch0, ch1);
        }
        lb = lbn;
    }

    // epilogue: thread map rows g,g+8; cols 2tc,2tc+1
    {
        float* po = g_part[ks];
        const int v = vt * 128 + vw + g;
        const int cha = 2 * tc;
        const int chb = 8 + 2 * tc;
        po[(size_t)cha * V + v]           = c0[0];
        po[(size_t)(cha + 1) * V + v]     = c0[1];
        po[(size_t)cha * V + v + 8]       = c0[2];
        po[(size_t)(cha + 1) * V + v + 8] = c0[3];
        po[(size_t)chb * V + v]           = c1[0];
        po[(size_t)(chb + 1) * V + v]     = c1[1];
        po[(size_t)chb * V + v + 8]       = c1[2];
        po[(size_t)(chb + 1) * V + v + 8] = c1[3];
    }
}

// ---------------- single persistent kernel ----------------
__global__ __launch_bounds__(256, 2)
void cheb_all(const float* __restrict__ x,
              const float* __restrict__ L,
              const float* __restrict__ Wt,
              const float* __restrict__ bias,
              float* __restrict__ out)
{
    extern __shared__ __align__(16) uint8_t smem[];
    const uint32_t sb = (uint32_t)__cvta_generic_to_shared(smem);

    const int t    = threadIdx.x;
    const int warp = t >> 5;
    const int lane = t & 31;
    const int vt   = blockIdx.x % 96;
    const int ks   = blockIdx.x / 96;
    const int gi   = blockIdx.x * 256 + t;

    const float* Bptr = x;

#pragma unroll 1
    for (int pass = 0; pass < 4; pass++) {
        pass_body(L, Bptr, sb, t, warp, lane, vt, ks);
        grid_barrier(t);                 // partials visible

        if (pass < 3) {
            if (gi < CV / 4) {
                const float4 s0 = ((const float4*)g_part[0])[gi];
                const float4 s1 = ((const float4*)g_part[1])[gi];
                const float4 s2 = ((const float4*)g_part[2])[gi];
                float4 r;
                r.x = s0.x + s1.x + s2.x;
                r.y = s0.y + s1.y + s2.y;
                r.z = s0.z + s1.z + s2.z;
                r.w = s0.w + s1.w + s2.w;
                if (pass > 0) {
                    const float* prev = (pass == 1) ? x : g_T[0];
                    const float4 pv = ((const float4*)prev)[gi];
                    r.x = 2.0f * r.x - pv.x;
                    r.y = 2.0f * r.y - pv.y;
                    r.z = 2.0f * r.z - pv.z;
                    r.w = 2.0f * r.w - pv.w;
                }
                ((float4*)g_T[pass])[gi] = r;
            }
            grid_barrier(t);
            Bptr = g_T[pass];
        }
    }

    // combine on first 48 CTAs (smem reused for W)
    if (blockIdx.x < V / 256) {
        float* Wsh = (float*)smem;
        float* bsh = Wsh + KORD * CIN * COUT;
        for (int idx = t; idx < KORD * CIN * COUT; idx += 256) Wsh[idx] = Wt[idx];
        if (t < COUT) bsh[t] = bias[t];
        __syncthreads();

        const int v = blockIdx.x * 256 + t;

        float acc[COUT];
#pragma unroll
        for (int o = 0; o < COUT; o++) acc[o] = bsh[o];

#pragma unroll
        for (int i = 0; i < CIN; i++) {
            const size_t iv = (size_t)i * V + v;
            float t2 = g_T[1][iv];
            float tv[KORD];
            tv[0] = x[iv];
            tv[1] = g_T[0][iv];
            tv[2] = t2;
            tv[3] = g_T[2][iv];
            tv[4] = 2.0f * (g_part[0][iv] + g_part[1][iv] + g_part[2][iv]) - t2;
#pragma unroll
            for (int k = 0; k < KORD; k++) {
                const float* wrow = &Wsh[(k * CIN + i) * COUT];
#pragma unroll
                for (int o = 0; o < COUT; o++) acc[o] = fmaf(tv[k], wrow[o], acc[o]);
            }
        }
#pragma unroll
        for (int o = 0; o < COUT; o++) out[(size_t)o * V + v] = acc[o];
    }
}

extern "C" void kernel_launch(void* const* d_in, const int* in_sizes, int n_in,
                              void* d_out, int out_size)
{
    const float* x  = (const float*)d_in[0];
    const float* L  = (const float*)d_in[1];
    const float* Wt = (const float*)d_in[2];
    const float* b  = (const float*)d_in[3];
    float* out = (float*)d_out;

    cudaFuncSetAttribute(cheb_all, cudaFuncAttributeMaxDynamicSharedMemorySize,
                         SMEM_DYN);

    cheb_all<<<NCTA, 256, SMEM_DYN>>>(x, L, Wt, b, out);
}

// round 13
// speedup vs baseline: 1.0251x; 1.0251x over previous
#include <cuda_runtime.h>
#include <cstdint>

#define V 12288
#define CIN 16
#define COUT 32
#define KORD 5
#define NKS 3               // k-slices per pass  -> 96*3 = 288 CTAs = 1 wave @2/SM
#define KSL (V / NKS)       // 4096
#define CHK 64              // u per chunk
#define NCHK (KSL / CHK)    // 64
#define CV (CIN * V)
#define RSB 144             // B smem row stride bytes (conflict-free frags)
#define AST 272             // A (fp32) smem row stride bytes (16B-mult, 2-wf LDS.64)
#define NCTA (96 * NKS)     // 288

// fp32 scratch: T1..T3, per-kslice partials, grid-barrier counter
__device__ float g_T[3][CV];
__device__ float g_part[NKS][CV];
__device__ unsigned g_bar;   // monotonic (288 incr per barrier) -> graph-replay safe

// smem layout: 3 x A fp32 stage (128*272) | 2 x B split stage (BH 2304 + BL 2304)
#define A_STG  (128 * AST)            // 34816
#define B_OFF  (3 * A_STG)            // 104448
#define B_STG  (2 * 16 * RSB)         // 4608 (BH+BL)
#define BL_REL (16 * RSB)             // 2304
#define SMEM_DYN (B_OFF + 2 * B_STG)  // 113664

__device__ __forceinline__ uint32_t lds32(uint32_t a) {
    uint32_t v;
    asm volatile("ld.shared.b32 %0, [%1];" : "=r"(v) : "r"(a));
    return v;
}
__device__ __forceinline__ uint2 lds64(uint32_t a) {
    uint2 v;
    asm volatile("ld.shared.v2.u32 {%0,%1}, [%2];" : "=r"(v.x), "=r"(v.y) : "r"(a));
    return v;
}
__device__ __forceinline__ void sts64(uint32_t a, uint32_t w0, uint32_t w1) {
    asm volatile("st.shared.v2.b32 [%0], {%1,%2};" :: "r"(a), "r"(w0), "r"(w1) : "memory");
}
__device__ __forceinline__ void cp_async16(uint32_t dst, const void* src) {
    asm volatile("cp.async.cg.shared.global [%0], [%1], 16;\n" :: "r"(dst), "l"(src));
}
__device__ __forceinline__ void cp_commit() {
    asm volatile("cp.async.commit_group;\n");
}
template <int N>
__device__ __forceinline__ void cp_wait() {
    asm volatile("cp.async.wait_group %0;\n" :: "n"(N));
}

// split one fp32 pair -> bf16-hi pair (truncate) + bf16-lo pair (residual, RN)
__device__ __forceinline__ void split2(uint2 p, uint32_t& h, uint32_t& l) {
    h = __byte_perm(p.x, p.y, 0x7632);
    float l0 = __uint_as_float(p.x) - __uint_as_float(p.x & 0xFFFF0000u);
    float l1 = __uint_as_float(p.y) - __uint_as_float(p.y & 0xFFFF0000u);
    asm("cvt.rn.bf16x2.f32 %0, %1, %2;" : "=r"(l) : "f"(l1), "f"(l0));
}

// split fp32 x4 -> hi/lo tiles (B staging only)
__device__ __forceinline__ void split_sts(float4 f, uint32_t ah, uint32_t al) {
    uint32_t b0 = __float_as_uint(f.x), b1 = __float_as_uint(f.y);
    uint32_t b2 = __float_as_uint(f.z), b3 = __float_as_uint(f.w);
    uint32_t h0 = __byte_perm(b0, b1, 0x7632);
    uint32_t h1 = __byte_perm(b2, b3, 0x7632);
    float l0 = f.x - __uint_as_float(b0 & 0xFFFF0000u);
    float l1 = f.y - __uint_as_float(b1 & 0xFFFF0000u);
    float l2 = f.z - __uint_as_float(b2 & 0xFFFF0000u);
    float l3 = f.w - __uint_as_float(b3 & 0xFFFF0000u);
    uint32_t w0, w1;
    asm("cvt.rn.bf16x2.f32 %0, %1, %2;" : "=r"(w0) : "f"(l1), "f"(l0));
    asm("cvt.rn.bf16x2.f32 %0, %1, %2;" : "=r"(w1) : "f"(l3), "f"(l2));
    sts64(ah, h0, h1);
    sts64(al, w0, w1);
}

__device__ __forceinline__ void mma_bf16(float* c, uint32_t a0, uint32_t a1,
                                         uint32_t a2, uint32_t a3,
                                         uint32_t b0, uint32_t b1) {
    asm volatile("mma.sync.aligned.m16n8k16.row.col.f32.bf16.bf16.f32 "
                 "{%0,%1,%2,%3}, {%4,%5,%6,%7}, {%8,%9}, {%0,%1,%2,%3};"
                 : "+f"(c[0]), "+f"(c[1]), "+f"(c[2]), "+f"(c[3])
                 : "r"(a0), "r"(a1), "r"(a2), "r"(a3), "r"(b0), "r"(b1));
}

// software grid barrier: 288 CTAs co-resident (one wave); monotonic counter
__device__ __forceinline__ void grid_barrier(int tid) {
    __syncthreads();
    if (tid == 0) {
        __threadfence();
        unsigned old = atomicAdd(&g_bar, 1u) + 1u;
        unsigned target = ((old + (NCTA - 1u)) / NCTA) * NCTA;
        for (;;) {
            unsigned cur;
            asm volatile("ld.global.acquire.gpu.u32 %0, [%1];"
                         : "=r"(cur) : "l"(&g_bar));
            if (cur >= target) break;
            __nanosleep(64);
        }
    }
    __syncthreads();
}

// ---------------- pass body (cp.async A pipeline, 3-stage, relaxed wait) ----------------
__device__ __forceinline__ void pass_body(
    const float* __restrict__ L, const float* __restrict__ B,
    uint32_t sb, int t, int warp, int lane, int vt, int ks)
{
    const int g    = lane >> 2;
    const int tc   = lane & 3;
    const int ub   = ks * KSL;

    // staging maps
    const int rh = t >> 4;           // 0..15
    const int cq = t & 15;           // 16B quad
    const float* Ag = L + (size_t)(vt * 128 + rh) * V + ub + cq * 4;
    const float* Bg = B + (size_t)rh * V + ub + cq * 4;
    const uint32_t a_dst = sb + (uint32_t)(rh * AST + cq * 16);   // + j*16*AST + buf
    const uint32_t b_dst = sb + B_OFF + (uint32_t)(rh * RSB + cq * 8);

    // fragment offsets
    const int vw = warp * 16;
    const uint32_t a_frag = sb + (uint32_t)((vw + g) * AST + tc * 8);
    const uint32_t b_frag = sb + B_OFF + (uint32_t)(g * RSB + tc * 4);

    float c0[4] = {0.f, 0.f, 0.f, 0.f};
    float c1[4] = {0.f, 0.f, 0.f, 0.f};

    // ---- prologue ----
    {
        float4 t0 = __ldg((const float4*)(Bg));          // B[0]
        split_sts(t0, b_dst, b_dst + BL_REL);            // -> Bbuf0
    }
    float4 lb = __ldg((const float4*)(Bg + CHK));        // B[1]
#pragma unroll
    for (int j = 0; j < 8; j++)                          // A[0] -> Abuf0
        cp_async16(a_dst + j * (16 * AST), Ag + (size_t)j * 16 * V);
    cp_commit();
#pragma unroll
    for (int j = 0; j < 8; j++)                          // A[1] -> Abuf1
        cp_async16(a_dst + A_STG + j * (16 * AST), Ag + (size_t)j * 16 * V + CHK);
    cp_commit();

#pragma unroll 1
    for (int c = 0; c < NCHK; c++) {
        float4 lbn;
        if (c + 2 < NCHK) lbn = __ldg((const float4*)(Bg + (c + 2) * CHK));

        // FIX vs R12: wait only for A[c]; keep A[c+1] in flight.
        if (c + 1 < NCHK) cp_wait<1>(); else cp_wait<0>();
        __syncthreads();       // publish A[c]; all warps done with compute c-1

        // stage B[c+1] -> Bbuf (c+1)%2 (reader compute c-1 finished)
        if (c + 1 < NCHK) {
            const uint32_t bo = b_dst + (uint32_t)(((c + 1) & 1) * B_STG);
            split_sts(lb, bo, bo + BL_REL);
        }
        // issue A[c+2] -> Abuf (c+2)%3 (reader compute c-1 finished)
        if (c + 2 < NCHK) {
            const uint32_t ao = a_dst + (uint32_t)(((c + 2) % 3) * A_STG);
            const float* as = Ag + (c + 2) * CHK;
#pragma unroll
            for (int j = 0; j < 8; j++)
                cp_async16(ao + j * (16 * AST), as + (size_t)j * 16 * V);
            cp_commit();
        }

        // compute chunk c: A fp32 frags split in-register
        const uint32_t abuf = a_frag + (uint32_t)((c % 3) * A_STG);
        const uint32_t bbuf = b_frag + (uint32_t)((c & 1) * B_STG);
#pragma unroll
        for (int s = 0; s < 4; s++) {
            const uint32_t ao = abuf + s * 64;
            const uint32_t bo = bbuf + s * 32;

            uint2 p00 = lds64(ao);                    // row g,   k pair 2tc
            uint2 p10 = lds64(ao + 8 * AST);          // row g+8, k pair 2tc
            uint2 p01 = lds64(ao + 32);               // row g,   k pair 2tc+8
            uint2 p11 = lds64(ao + 8 * AST + 32);     // row g+8, k pair 2tc+8
            uint32_t ah0, al0, ah1, al1, ah2, al2, ah3, al3;
            split2(p00, ah0, al0);
            split2(p10, ah1, al1);
            split2(p01, ah2, al2);
            split2(p11, ah3, al3);

            uint32_t bh0 = lds32(bo);
            uint32_t bh1 = lds32(bo + 16);
            uint32_t bl0 = lds32(bo + BL_REL);
            uint32_t bl1 = lds32(bo + BL_REL + 16);
            mma_bf16(c0, ah0, ah1, ah2, ah3, bh0, bh1);
            mma_bf16(c0, ah0, ah1, ah2, ah3, bl0, bl1);
            mma_bf16(c0, al0, al1, al2, al3, bh0, bh1);

            uint32_t ch0 = lds32(bo + 8 * RSB);
            uint32_t ch1 = lds32(bo + 8 * RSB + 16);
            uint32_t cl0 = lds32(bo + BL_REL + 8 * RSB);
            uint32_t cl1 = lds32(bo + BL_REL + 8 * RSB + 16);
            mma_bf16(c1, ah0, ah1, ah2, ah3, ch0, ch1);
            mma_bf16(c1, ah0, ah1, ah2, ah3, cl0, cl1);
            mma_bf16(c1, al0, al1, al2, al3, ch0, ch1);
        }
        lb = lbn;
    }

    // epilogue: thread map rows g,g+8; cols 2tc,2tc+1
    {
        float* po = g_part[ks];
        const int v = vt * 128 + vw + g;
        const int cha = 2 * tc;
        const int chb = 8 + 2 * tc;
        po[(size_t)cha * V + v]           = c0[0];
        po[(size_t)(cha + 1) * V + v]     = c0[1];
        po[(size_t)cha * V + v + 8]       = c0[2];
        po[(size_t)(cha + 1) * V + v + 8] = c0[3];
        po[(size_t)chb * V + v]           = c1[0];
        po[(size_t)(chb + 1) * V + v]     = c1[1];
        po[(size_t)chb * V + v + 8]       = c1[2];
        po[(size_t)(chb + 1) * V + v + 8] = c1[3];
    }
}

// ---------------- single persistent kernel ----------------
__global__ __launch_bounds__(256, 2)
void cheb_all(const float* __restrict__ x,
              const float* __restrict__ L,
              const float* __restrict__ Wt,
              const float* __restrict__ bias,
              float* __restrict__ out)
{
    extern __shared__ __align__(16) uint8_t smem[];
    const uint32_t sb = (uint32_t)__cvta_generic_to_shared(smem);

    const int t    = threadIdx.x;
    const int warp = t >> 5;
    const int lane = t & 31;
    const int vt   = blockIdx.x % 96;
    const int ks   = blockIdx.x / 96;
    const int gi   = blockIdx.x * 256 + t;

    const float* Bptr = x;

#pragma unroll 1
    for (int pass = 0; pass < 4; pass++) {
        pass_body(L, Bptr, sb, t, warp, lane, vt, ks);
        grid_barrier(t);                 // partials visible

        if (pass < 3) {
            if (gi < CV / 4) {
                const float4 s0 = ((const float4*)g_part[0])[gi];
                const float4 s1 = ((const float4*)g_part[1])[gi];
                const float4 s2 = ((const float4*)g_part[2])[gi];
                float4 r;
                r.x = s0.x + s1.x + s2.x;
                r.y = s0.y + s1.y + s2.y;
                r.z = s0.z + s1.z + s2.z;
                r.w = s0.w + s1.w + s2.w;
                if (pass > 0) {
                    const float* prev = (pass == 1) ? x : g_T[0];
                    const float4 pv = ((const float4*)prev)[gi];
                    r.x = 2.0f * r.x - pv.x;
                    r.y = 2.0f * r.y - pv.y;
                    r.z = 2.0f * r.z - pv.z;
                    r.w = 2.0f * r.w - pv.w;
                }
                ((float4*)g_T[pass])[gi] = r;
            }
            grid_barrier(t);
            Bptr = g_T[pass];
        }
    }

    // combine on first 48 CTAs (smem reused for W)
    if (blockIdx.x < V / 256) {
        float* Wsh = (float*)smem;
        float* bsh = Wsh + KORD * CIN * COUT;
        for (int idx = t; idx < KORD * CIN * COUT; idx += 256) Wsh[idx] = Wt[idx];
        if (t < COUT) bsh[t] = bias[t];
        __syncthreads();

        const int v = blockIdx.x * 256 + t;

        float acc[COUT];
#pragma unroll
        for (int o = 0; o < COUT; o++) acc[o] = bsh[o];

#pragma unroll
        for (int i = 0; i < CIN; i++) {
            const size_t iv = (size_t)i * V + v;
            float t2 = g_T[1][iv];
            float tv[KORD];
            tv[0] = x[iv];
            tv[1] = g_T[0][iv];
            tv[2] = t2;
            tv[3] = g_T[2][iv];
            tv[4] = 2.0f * (g_part[0][iv] + g_part[1][iv] + g_part[2][iv]) - t2;
#pragma unroll
            for (int k = 0; k < KORD; k++) {
                const float* wrow = &Wsh[(k * CIN + i) * COUT];
#pragma unroll
                for (int o = 0; o < COUT; o++) acc[o] = fmaf(tv[k], wrow[o], acc[o]);
            }
        }
#pragma unroll
        for (int o = 0; o < COUT; o++) out[(size_t)o * V + v] = acc[o];
    }
}

extern "C" void kernel_launch(void* const* d_in, const int* in_sizes, int n_in,
                              void* d_out, int out_size)
{
    const float* x  = (const float*)d_in[0];
    const float* L  = (const float*)d_in[1];
    const float* Wt = (const float*)d_in[2];
    const float* b  = (const float*)d_in[3];
    float* out = (float*)d_out;

    cudaFuncSetAttribute(cheb_all, cudaFuncAttributeMaxDynamicSharedMemorySize,
                         SMEM_DYN);

    cheb_all<<<NCTA, 256, SMEM_DYN>>>(x, L, Wt, b, out);
}

// round 14
// speedup vs baseline: 1.1490x; 1.1209x over previous
#include <cuda_runtime.h>
#include <cstdint>

#define V 12288
#define CIN 16
#define COUT 32
#define KORD 5
#define NKS 3               // k-slices per pass  -> 96*3 = 288 CTAs = 1 wave @2/SM
#define KSL (V / NKS)       // 4096
#define CHK 64              // u per chunk
#define NCHK (KSL / CHK)    // 64
#define CV (CIN * V)
#define RS 72               // smem row stride in bf16 elements
#define RSB (RS * 2)        // 144 bytes
#define NCTA (96 * NKS)     // 288

// fp32 scratch: T1..T3, per-kslice partials, grid-barrier counter
__device__ float g_T[3][CV];
__device__ float g_part[NKS][CV];
__device__ unsigned g_bar;   // monotonic (288 incr per barrier) -> graph-replay safe

// per-stage smem byte offsets
#define AH_OFF 0
#define AL_OFF (128 * RSB)            // 18432
#define BH_OFF (2 * 128 * RSB)        // 36864
#define BL_OFF (BH_OFF + 16 * RSB)    // 39168
#define STAGE  (BL_OFF + 16 * RSB)    // 41472 per stage
#define SMEM_DYN (2 * STAGE)          // 82944

__device__ __forceinline__ uint32_t lds32(uint32_t a) {
    uint32_t v;
    asm volatile("ld.shared.b32 %0, [%1];" : "=r"(v) : "r"(a));
    return v;
}
__device__ __forceinline__ void sts64(uint32_t a, uint32_t w0, uint32_t w1) {
    asm volatile("st.shared.v2.b32 [%0], {%1,%2};" :: "r"(a), "r"(w0), "r"(w1) : "memory");
}

// split fp32 x4 -> bf16 hi (truncate) + bf16 lo (residual, RN); store 8B to each tile
__device__ __forceinline__ void split_sts(float4 f, uint32_t ah, uint32_t al) {
    uint32_t b0 = __float_as_uint(f.x), b1 = __float_as_uint(f.y);
    uint32_t b2 = __float_as_uint(f.z), b3 = __float_as_uint(f.w);
    uint32_t h0 = __byte_perm(b0, b1, 0x7632);
    uint32_t h1 = __byte_perm(b2, b3, 0x7632);
    float l0 = f.x - __uint_as_float(b0 & 0xFFFF0000u);
    float l1 = f.y - __uint_as_float(b1 & 0xFFFF0000u);
    float l2 = f.z - __uint_as_float(b2 & 0xFFFF0000u);
    float l3 = f.w - __uint_as_float(b3 & 0xFFFF0000u);
    uint32_t w0, w1;
    asm("cvt.rn.bf16x2.f32 %0, %1, %2;" : "=r"(w0) : "f"(l1), "f"(l0));
    asm("cvt.rn.bf16x2.f32 %0, %1, %2;" : "=r"(w1) : "f"(l3), "f"(l2));
    sts64(ah, h0, h1);
    sts64(al, w0, w1);
}

__device__ __forceinline__ void mma_bf16(float* c, uint32_t a0, uint32_t a1,
                                         uint32_t a2, uint32_t a3,
                                         uint32_t b0, uint32_t b1) {
    asm volatile("mma.sync.aligned.m16n8k16.row.col.f32.bf16.bf16.f32 "
                 "{%0,%1,%2,%3}, {%4,%5,%6,%7}, {%8,%9}, {%0,%1,%2,%3};"
                 : "+f"(c[0]), "+f"(c[1]), "+f"(c[2]), "+f"(c[3])
                 : "r"(a0), "r"(a1), "r"(a2), "r"(a3), "r"(b0), "r"(b1));
}

// software grid barrier: 288 CTAs co-resident (one wave); monotonic counter
__device__ __forceinline__ void grid_barrier(int tid) {
    __syncthreads();
    if (tid == 0) {
        __threadfence();
        unsigned old = atomicAdd(&g_bar, 1u) + 1u;
        unsigned target = ((old + (NCTA - 1u)) / NCTA) * NCTA;
        for (;;) {
            unsigned cur;
            asm volatile("ld.global.acquire.gpu.u32 %0, [%1];"
                         : "=r"(cur) : "l"(&g_bar));
            if (cur >= target) break;
            __nanosleep(64);
        }
    }
    __syncthreads();
}

// ---------------- pass body (R11 engine + interleaved stage/prefetch) ----------------
__device__ __forceinline__ void pass_body(
    const float* __restrict__ L, const float* __restrict__ B,
    uint32_t sb, int t, int warp, int lane, int vt, int ks)
{
    const int g    = lane >> 2;
    const int tc   = lane & 3;
    const int ub   = ks * KSL;

    const int rh = t >> 4;
    const int cq = t & 15;
    const float* Ag = L + (size_t)(vt * 128 + rh) * V + ub + cq * 4;
    const float* Bg = B + (size_t)rh * V + ub + cq * 4;
    const uint32_t st_off = (uint32_t)(rh * RSB + cq * 8);

    const int vw = warp * 16;
    const uint32_t a_frag = (uint32_t)((vw + g) * RSB + tc * 4);
    const uint32_t b_frag = (uint32_t)(g * RSB + tc * 4);

    float c0[4] = {0.f, 0.f, 0.f, 0.f};
    float c1[4] = {0.f, 0.f, 0.f, 0.f};

    float4 la[8];
    float4 lb;

    // prologue: load+stage chunk 0, load chunk 1
    lb = __ldg((const float4*)(Bg));
#pragma unroll
    for (int j = 0; j < 8; j++)
        la[j] = __ldcs((const float4*)(Ag + (size_t)j * 16 * V));
    {
#pragma unroll
        for (int j = 0; j < 8; j++)
            split_sts(la[j], sb + AH_OFF + st_off + j * 2304,
                             sb + AL_OFF + st_off + j * 2304);
        split_sts(lb, sb + BH_OFF + st_off, sb + BL_OFF + st_off);
    }
    lb = __ldg((const float4*)(Bg + CHK));
#pragma unroll
    for (int j = 0; j < 8; j++)
        la[j] = __ldcs((const float4*)(Ag + (size_t)j * 16 * V + CHK));
    __syncthreads();

#pragma unroll 1
    for (int c = 0; c < NCHK; c++) {
        const uint32_t sbuf = sb + (uint32_t)(c & 1) * STAGE;

        // stage chunk c+1 into the other buffer; reload each register
        // immediately after its store consumes it (early LDG issue -> smoother
        // DRAM demand; same registers, same semantics as R11).
        if (c + 1 < NCHK) {
            const uint32_t so = sb + (uint32_t)(((c + 1) & 1) * STAGE);
            const bool pf = (c + 2 < NCHK);
            const int off = (c + 2) * CHK;
            split_sts(lb, so + BH_OFF + st_off, so + BL_OFF + st_off);
            if (pf) lb = __ldg((const float4*)(Bg + off));
#pragma unroll
            for (int j = 0; j < 8; j++) {
                split_sts(la[j], so + AH_OFF + st_off + j * 2304,
                                 so + AL_OFF + st_off + j * 2304);
                if (pf) la[j] = __ldcs((const float4*)(Ag + (size_t)j * 16 * V + off));
            }
        }

        // compute chunk c: 4 k-steps x (2 n-tiles x 3 products)
#pragma unroll
        for (int s = 0; s < 4; s++) {
            const uint32_t ao = sbuf + a_frag + s * 32;
            const uint32_t bo = sbuf + b_frag + s * 32;
            uint32_t ah0 = lds32(ao + AH_OFF);
            uint32_t ah1 = lds32(ao + AH_OFF + 8 * RSB);
            uint32_t ah2 = lds32(ao + AH_OFF + 16);
            uint32_t ah3 = lds32(ao + AH_OFF + 8 * RSB + 16);
            uint32_t al0 = lds32(ao + AL_OFF);
            uint32_t al1 = lds32(ao + AL_OFF + 8 * RSB);
            uint32_t al2 = lds32(ao + AL_OFF + 16);
            uint32_t al3 = lds32(ao + AL_OFF + 8 * RSB + 16);

            uint32_t bh0 = lds32(bo + BH_OFF);
            uint32_t bh1 = lds32(bo + BH_OFF + 16);
            uint32_t bl0 = lds32(bo + BL_OFF);
            uint32_t bl1 = lds32(bo + BL_OFF + 16);
            mma_bf16(c0, ah0, ah1, ah2, ah3, bh0, bh1);
            mma_bf16(c0, ah0, ah1, ah2, ah3, bl0, bl1);
            mma_bf16(c0, al0, al1, al2, al3, bh0, bh1);

            uint32_t ch0 = lds32(bo + BH_OFF + 8 * RSB);
            uint32_t ch1 = lds32(bo + BH_OFF + 8 * RSB + 16);
            uint32_t cl0 = lds32(bo + BL_OFF + 8 * RSB);
            uint32_t cl1 = lds32(bo + BL_OFF + 8 * RSB + 16);
            mma_bf16(c1, ah0, ah1, ah2, ah3, ch0, ch1);
            mma_bf16(c1, ah0, ah1, ah2, ah3, cl0, cl1);
            mma_bf16(c1, al0, al1, al2, al3, ch0, ch1);
        }
        __syncthreads();
    }

    // epilogue: thread map rows g,g+8; cols 2tc,2tc+1
    {
        float* po = g_part[ks];
        const int v = vt * 128 + vw + g;
        const int cha = 2 * tc;
        const int chb = 8 + 2 * tc;
        po[(size_t)cha * V + v]           = c0[0];
        po[(size_t)(cha + 1) * V + v]     = c0[1];
        po[(size_t)cha * V + v + 8]       = c0[2];
        po[(size_t)(cha + 1) * V + v + 8] = c0[3];
        po[(size_t)chb * V + v]           = c1[0];
        po[(size_t)(chb + 1) * V + v]     = c1[1];
        po[(size_t)chb * V + v + 8]       = c1[2];
        po[(size_t)(chb + 1) * V + v + 8] = c1[3];
    }
}

// ---------------- single persistent kernel ----------------
__global__ __launch_bounds__(256, 2)
void cheb_all(const float* __restrict__ x,
              const float* __restrict__ L,
              const float* __restrict__ Wt,
              const float* __restrict__ bias,
              float* __restrict__ out)
{
    extern __shared__ __align__(16) uint8_t smem[];
    const uint32_t sb = (uint32_t)__cvta_generic_to_shared(smem);

    const int t    = threadIdx.x;
    const int warp = t >> 5;
    const int lane = t & 31;
    const int vt   = blockIdx.x % 96;
    const int ks   = blockIdx.x / 96;
    const int gi   = blockIdx.x * 256 + t;

    const float* Bptr = x;

#pragma unroll 1
    for (int pass = 0; pass < 4; pass++) {
        pass_body(L, Bptr, sb, t, warp, lane, vt, ks);
        grid_barrier(t);                 // partials visible

        if (pass < 3) {
            if (gi < CV / 4) {
                const float4 s0 = ((const float4*)g_part[0])[gi];
                const float4 s1 = ((const float4*)g_part[1])[gi];
                const float4 s2 = ((const float4*)g_part[2])[gi];
                float4 r;
                r.x = s0.x + s1.x + s2.x;
                r.y = s0.y + s1.y + s2.y;
                r.z = s0.z + s1.z + s2.z;
                r.w = s0.w + s1.w + s2.w;
                if (pass > 0) {
                    const float* prev = (pass == 1) ? x : g_T[0];
                    const float4 pv = ((const float4*)prev)[gi];
                    r.x = 2.0f * r.x - pv.x;
                    r.y = 2.0f * r.y - pv.y;
                    r.z = 2.0f * r.z - pv.z;
                    r.w = 2.0f * r.w - pv.w;
                }
                ((float4*)g_T[pass])[gi] = r;
            }
            grid_barrier(t);
            Bptr = g_T[pass];
        }
    }

    // combine on first 96 CTAs: CTA handles one v-block x one o-half (16 outputs)
    if (blockIdx.x < 2 * (V / 256)) {
        const int oh = blockIdx.x / (V / 256);   // 0 or 1
        const int vb = blockIdx.x % (V / 256);

        float* Wsh = (float*)smem;               // 16 outputs per (k,i) row
        float* bsh = Wsh + KORD * CIN * 16;
        for (int idx = t; idx < KORD * CIN * 16; idx += 256) {
            int ki = idx >> 4;
            int o  = idx & 15;
            Wsh[idx] = Wt[ki * COUT + oh * 16 + o];
        }
        if (t < 16) bsh[t] = bias[oh * 16 + t];
        __syncthreads();

        const int v = vb * 256 + t;

        float acc[16];
#pragma unroll
        for (int o = 0; o < 16; o++) acc[o] = bsh[o];

#pragma unroll
        for (int i = 0; i < CIN; i++) {
            const size_t iv = (size_t)i * V + v;
            float t2 = g_T[1][iv];
            float tv[KORD];
            tv[0] = x[iv];
            tv[1] = g_T[0][iv];
            tv[2] = t2;
            tv[3] = g_T[2][iv];
            tv[4] = 2.0f * (g_part[0][iv] + g_part[1][iv] + g_part[2][iv]) - t2;
#pragma unroll
            for (int k = 0; k < KORD; k++) {
                const float* wrow = &Wsh[(k * CIN + i) * 16];
#pragma unroll
                for (int o = 0; o < 16; o++) acc[o] = fmaf(tv[k], wrow[o], acc[o]);
            }
        }
#pragma unroll
        for (int o = 0; o < 16; o++)
            out[(size_t)(oh * 16 + o) * V + v] = acc[o];
    }
}

extern "C" void kernel_launch(void* const* d_in, const int* in_sizes, int n_in,
                              void* d_out, int out_size)
{
    const float* x  = (const float*)d_in[0];
    const float* L  = (const float*)d_in[1];
    const float* Wt = (const float*)d_in[2];
    const float* b  = (const float*)d_in[3];
    float* out = (float*)d_out;

    cudaFuncSetAttribute(cheb_all, cudaFuncAttributeMaxDynamicSharedMemorySize,
                         SMEM_DYN);

    cheb_all<<<NCTA, 256, SMEM_DYN>>>(x, L, Wt, b, out);
}